// round 16
// baseline (speedup 1.0000x reference)
#include <cuda_runtime.h>

// LSTM scan: T=2048, B=2048, IN=5, H=10.
// R10 resubmit (previous round died on GB300 container infra, kernel never
// ran). A/B of h-exchange mechanism: R8's smem STS->LDS replaced by 10
// SHFL.IDX + 5 packs.
//   R9 proved the wall is pure per-warp chain latency (geometry-invariant
//   335 cyc/step). Biggest unmeasured chain constant: smem has NO store-
//   forwarding, so the chain-critical LDS waits for the prior STS to commit
//   (+~30-60 cyc) + LDS lat 29. SHFL is reg->reg: first h at lat 26, no
//   commit wait. Clean A/B of the exchange mechanism on the lean datapath.
// Kept from R8: 2-warp blocks (342), PF=4 raw-x ring, prescaled i/f/o
// weights, 3+2 split h-dot + fadd2, pre-packed bias, MUFU.TANH, f32x2 math.

#define T_STEPS 2048
#define BATCH   2048
#define IN_DIM  5
#define HID     10
#define BPW     3                               // batches per warp (30 lanes)
#define WARPS   2
#define NTHREADS (WARPS * 32)                   // 64
#define BPB     (WARPS * BPW)                   // 6 batches per block
#define NBLOCKS ((BATCH + BPB - 1) / BPB)       // 342
#define PF      4                               // x prefetch depth (divides T)

typedef unsigned long long u64;

__device__ __forceinline__ u64 pack2(float lo, float hi) {
    u64 r;
    asm("mov.b64 %0, {%1, %2};" : "=l"(r) : "f"(lo), "f"(hi));
    return r;
}
__device__ __forceinline__ void unpack2(u64 v, float& lo, float& hi) {
    asm("mov.b64 {%0, %1}, %2;" : "=f"(lo), "=f"(hi) : "l"(v));
}
__device__ __forceinline__ u64 ffma2(u64 a, u64 b, u64 c) {
    u64 d;
    asm("fma.rn.f32x2 %0, %1, %2, %3;" : "=l"(d) : "l"(a), "l"(b), "l"(c));
    return d;
}
__device__ __forceinline__ u64 fmul2(u64 a, u64 b) {
    u64 d;
    asm("mul.rn.f32x2 %0, %1, %2;" : "=l"(d) : "l"(a), "l"(b));
    return d;
}
__device__ __forceinline__ u64 fadd2(u64 a, u64 b) {
    u64 d;
    asm("add.rn.f32x2 %0, %1, %2;" : "=l"(d) : "l"(a), "l"(b));
    return d;
}
__device__ __forceinline__ float tanha(float z) {
    float r;
    asm("tanh.approx.f32 %0, %1;" : "=f"(r) : "f"(z));
    return r;
}
// weights already prescaled by 0.5 for sigmoid gates:
__device__ __forceinline__ float fsig_pre(float zh) {   // zh = 0.5*z
    return fmaf(0.5f, tanha(zh), 0.5f);
}

// One LSTM step. DOPF: issue the x prefetch for PF steps ahead.
// h exchange: 10 SHFL.IDX of the previous step's hcur (reg->reg, no smem
// commit wait), ordered hp0..hp4 to match the 3+2 dot consumption order.
#define STEP_BODY(d, DOPF) do {                                               \
    /* chain head: gather previous step's h from peer lanes */                \
    const float hv0 = __shfl_sync(0xFFFFFFFFu, hcur, base + 0);               \
    const float hv1 = __shfl_sync(0xFFFFFFFFu, hcur, base + 1);               \
    const float hv2 = __shfl_sync(0xFFFFFFFFu, hcur, base + 2);               \
    const float hv3 = __shfl_sync(0xFFFFFFFFu, hcur, base + 3);               \
    const float hv4 = __shfl_sync(0xFFFFFFFFu, hcur, base + 4);               \
    const float hv5 = __shfl_sync(0xFFFFFFFFu, hcur, base + 5);               \
    const float hv6 = __shfl_sync(0xFFFFFFFFu, hcur, base + 6);               \
    const float hv7 = __shfl_sync(0xFFFFFFFFu, hcur, base + 7);               \
    const float hv8 = __shfl_sync(0xFFFFFFFFu, hcur, base + 8);               \
    const float hv9 = __shfl_sync(0xFFFFFFFFu, hcur, base + 9);               \
    float nx0, nx1, nx2, nx3, nx4;                                            \
    if (DOPF) {                       /* compile-time constant */             \
        nx0 = __ldg(xpf + 0); nx1 = __ldg(xpf + 1); nx2 = __ldg(xpf + 2);     \
        nx3 = __ldg(xpf + 3); nx4 = __ldg(xpf + 4);                           \
        xpf += xstep;                                                         \
    }                                                                         \
    const u64 hp0 = pack2(hv0, hv1), hp1 = pack2(hv2, hv3);                   \
    const u64 hp2 = pack2(hv4, hv5), hp3 = pack2(hv6, hv7);                   \
    const u64 hp4 = pack2(hv8, hv9);                                          \
    const u64 v0 = pack2(xr[d][0], xr[d][1]);                                 \
    const u64 v1 = pack2(xr[d][2], xr[d][3]);                                 \
    const u64 v2 = pack2(xr[d][4], 0.0f);                                     \
    float gate[4];                                                            \
    _Pragma("unroll")                                                         \
    for (int q = 0; q < 4; q++) {                                             \
        u64 accA = biasp[q];          /* x-part retires during shfl wait */   \
        accA = ffma2(wp[q][0], v0, accA);                                     \
        accA = ffma2(wp[q][1], v1, accA);                                     \
        accA = ffma2(wp[q][2], v2, accA);                                     \
        accA = ffma2(wp[q][3], hp0, accA);                                    \
        accA = ffma2(wp[q][4], hp1, accA);                                    \
        accA = ffma2(wp[q][5], hp2, accA);                                    \
        u64 accB = fmul2(wp[q][6], hp3);   /* parallel 2-chain */             \
        accB = ffma2(wp[q][7], hp4, accB);                                    \
        const u64 acc = fadd2(accA, accB);                                    \
        float lo_, hi_; unpack2(acc, lo_, hi_);                               \
        gate[q] = lo_ + hi_;                                                  \
    }                                                                         \
    const float is = fsig_pre(gate[0]);                                       \
    const float fs = fsig_pre(gate[1]);                                       \
    const float gt = tanha(gate[2]);                                          \
    const float os = fsig_pre(gate[3]);                                       \
    c = fs * c + is * gt;                                                     \
    const float hn = os * tanha(c);                                           \
    hcur = hn;                        /* feeds next step's shfls */           \
    if (active) *op = hn;             /* fire-and-forget */                   \
    op += ostep;                                                              \
    if (DOPF) {                                                               \
        xr[d][0] = nx0; xr[d][1] = nx1; xr[d][2] = nx2;                       \
        xr[d][3] = nx3; xr[d][4] = nx4;                                       \
    }                                                                         \
} while (0)

__global__ void __launch_bounds__(NTHREADS, 1) lstm_scan_kernel(
    const float* __restrict__ x,     // [T, B, IN]
    const float* __restrict__ hx0,   // [B, H]
    const float* __restrict__ cx0,   // [B, H]
    const float* __restrict__ Wih,   // [4H, IN]
    const float* __restrict__ Whh,   // [4H, H]
    const float* __restrict__ bih,   // [4H]
    const float* __restrict__ bhh,   // [4H]
    float* __restrict__ out)         // [T*B, H]
{
    const int lane = threadIdx.x & 31;
    const int warp = threadIdx.x >> 5;
    const int g    = lane / HID;          // batch slot in warp (0..3)
    const int h    = lane % HID;          // hidden unit 0..9
    // shfl source base, clamped so lanes 30/31 read a valid group
    const int base = ((g < BPW) ? g : (BPW - 1)) * HID;

    const int  b_raw  = blockIdx.x * BPB + warp * BPW + g;
    const bool active = (g < BPW) && (b_raw < BATCH);
    const int  b      = active ? b_raw : (BATCH - 1);   // clamp: safe loads

    // Pack weights, v-layout [x0..x4, 0, h0..h9] (8 f32x2 per gate).
    // Gates i,f,o (q != 2) prescaled by 0.5 -> sigmoid needs no pre-mul.
    u64 wp[4][8];
    u64 biasp[4];
#pragma unroll
    for (int q = 0; q < 4; q++) {
        const float sc = (q == 2) ? 1.0f : 0.5f;
        const int r = q * HID + h;
        float wv[16];
#pragma unroll
        for (int k = 0; k < IN_DIM; k++) wv[k] = sc * Wih[r * IN_DIM + k];
        wv[5] = 0.0f;                                    // pad slot
#pragma unroll
        for (int j = 0; j < HID; j++) wv[6 + j] = sc * Whh[r * HID + j];
#pragma unroll
        for (int p = 0; p < 8; p++) wp[q][p] = pack2(wv[2 * p], wv[2 * p + 1]);
        biasp[q] = pack2(sc * (bih[r] + bhh[r]), 0.0f);
    }

    float c    = cx0[(size_t)b * HID + h];
    float hcur = hx0[(size_t)b * HID + h];   // own h; peers fetched via shfl

    // Preload x rows 0..PF-1 into the register ring.
    float xr[PF][IN_DIM];
#pragma unroll
    for (int d = 0; d < PF; d++) {
        const float* pp = x + ((size_t)d * BATCH + b) * IN_DIM;
#pragma unroll
        for (int k = 0; k < IN_DIM; k++) xr[d][k] = __ldg(pp + k);
    }

    const size_t xstep = (size_t)BATCH * IN_DIM;
    const size_t ostep = (size_t)BATCH * HID;
    const float* xpf = x + ((size_t)PF * BATCH + b) * IN_DIM;   // next fetch
    float* op = out + (size_t)b * HID + h;

    // Main loop: all chunks except the last prefetch unconditionally.
#pragma unroll 1
    for (int tc = 0; tc < T_STEPS - PF; tc += PF) {
#pragma unroll
        for (int d = 0; d < PF; d++) STEP_BODY(d, true);
    }
    // Peeled final chunk: consume the ring, no prefetch, no branches.
#pragma unroll
    for (int d = 0; d < PF; d++) STEP_BODY(d, false);
}

extern "C" void kernel_launch(void* const* d_in, const int* in_sizes, int n_in,
                              void* d_out, int out_size) {
    (void)in_sizes; (void)n_in; (void)out_size;
    const float* x   = (const float*)d_in[0];
    const float* hx0 = (const float*)d_in[1];
    const float* cx0 = (const float*)d_in[2];
    const float* Wih = (const float*)d_in[3];
    const float* Whh = (const float*)d_in[4];
    const float* bih = (const float*)d_in[5];
    const float* bhh = (const float*)d_in[6];
    float* out = (float*)d_out;

    lstm_scan_kernel<<<NBLOCKS, NTHREADS>>>(x, hx0, cx0, Wih, Whh, bih, bhh, out);
}